// round 1
// baseline (speedup 1.0000x reference)
#include <cuda_runtime.h>

#define BB   512   // batch
#define CC   512   // codes
#define KK   512   // dict size
#define EE   16    // embed dim
#define NT   128   // threads per block

#define Z_OFF   0
#define ZE_OFF  ((size_t)BB * CC * EE)            // 4,194,304
#define OH_OFF  ((size_t)2 * BB * CC * EE)        // 8,388,608

__device__ __forceinline__ unsigned long long pack2(float a, float b) {
    unsigned long long r;
    asm("mov.b64 %0, {%1, %2};" : "=l"(r) : "f"(a), "f"(b));
    return r;
}
__device__ __forceinline__ void fma2(unsigned long long &d,
                                     unsigned long long a,
                                     unsigned long long b) {
    asm("fma.rn.f32x2 %0, %1, %2, %0;" : "+l"(d) : "l"(a), "l"(b));
}
__device__ __forceinline__ void unpack2(float &lo, float &hi, unsigned long long v) {
    asm("mov.b64 {%0, %1}, %2;" : "=f"(lo), "=f"(hi) : "l"(v));
}

// Dynamic smem layout (71,680 bytes):
//   [0 .. 8192)  ull  sdup   : dict[c] duplicated pairs {v,v}, k-major (64 KB)
//   [8192..8704) ull  snh2   : {-0.5*||d_k||^2} duplicated pairs       (4 KB)
//   then 512 int  sidx       : per-row argmin                          (2 KB)
__global__ void __launch_bounds__(NT) vq_kernel(const float* __restrict__ mu,
                                                const float* __restrict__ dict,
                                                float* __restrict__ out)
{
    extern __shared__ unsigned long long smem_raw[];
    unsigned long long* sdup = smem_raw;                 // KK*EE entries
    unsigned long long* snh2 = smem_raw + KK * EE;       // KK entries
    int* sidx = (int*)(smem_raw + KK * EE + KK);         // BB entries

    const int c = blockIdx.x;
    const int t = threadIdx.x;

    // ---- load this thread's 4 batch rows, packed as f32x2 pairs ----
    unsigned long long muA[EE], muB[EE];
    {
        const float* m0 = mu + (size_t)(t)       * (CC * EE) + c * EE;
        const float* m1 = mu + (size_t)(t + 128) * (CC * EE) + c * EE;
        const float* m2 = mu + (size_t)(t + 256) * (CC * EE) + c * EE;
        const float* m3 = mu + (size_t)(t + 384) * (CC * EE) + c * EE;
#pragma unroll
        for (int e = 0; e < EE; e += 4) {
            float4 a = *(const float4*)(m0 + e);
            float4 b = *(const float4*)(m1 + e);
            float4 x = *(const float4*)(m2 + e);
            float4 y = *(const float4*)(m3 + e);
            muA[e + 0] = pack2(a.x, b.x);
            muA[e + 1] = pack2(a.y, b.y);
            muA[e + 2] = pack2(a.z, b.z);
            muA[e + 3] = pack2(a.w, b.w);
            muB[e + 0] = pack2(x.x, y.x);
            muB[e + 1] = pack2(x.y, y.y);
            muB[e + 2] = pack2(x.z, y.z);
            muB[e + 3] = pack2(x.w, y.w);
        }
    }

    // ---- dict[c] -> smem, duplicated pairs ----
    {
        const float4* g = (const float4*)(dict + (size_t)c * KK * EE);
#pragma unroll 4
        for (int i = t; i < KK * EE / 4; i += NT) {
            float4 v = g[i];
            sdup[i * 4 + 0] = pack2(v.x, v.x);
            sdup[i * 4 + 1] = pack2(v.y, v.y);
            sdup[i * 4 + 2] = pack2(v.z, v.z);
            sdup[i * 4 + 3] = pack2(v.w, v.w);
        }
    }

    // ---- zero this block's slice of one_hot (512 rows x 2KB), coalesced ----
    {
        float4 z4 = make_float4(0.f, 0.f, 0.f, 0.f);
        float4* ohbase = (float4*)(out + OH_OFF) + (size_t)c * (KK / 4) + t;
        const size_t row_stride = (size_t)CC * KK / 4;   // in float4
#pragma unroll 4
        for (int b = 0; b < BB; b++) {
            ohbase[(size_t)b * row_stride] = z4;
        }
    }
    __syncthreads();

    // ---- -0.5 * ||d_k||^2, duplicated ----
    {
        const float* sf = (const float*)sdup;   // stride-2 view (low halves)
        for (int k = t; k < KK; k += NT) {
            float s = 0.f;
#pragma unroll
            for (int e = 0; e < EE; e++) {
                float v = sf[(k * EE + e) * 2];
                s = fmaf(v, v, s);
            }
            snh2[k] = pack2(-0.5f * s, -0.5f * s);
        }
    }
    __syncthreads();

    // ---- main argmax loop over k (maximize dot - 0.5*||d||^2) ----
    float best0 = -3.4e38f, best1 = -3.4e38f, best2 = -3.4e38f, best3 = -3.4e38f;
    int i0 = 0, i1 = 0, i2 = 0, i3 = 0;

    for (int k = 0; k < KK; k += 2) {
        unsigned long long n0 = snh2[k];
        unsigned long long n1 = snh2[k + 1];
        unsigned long long a0 = n0, b0 = n0;   // rows (t, t+128) for k, k+1
        unsigned long long a1 = n1, b1 = n1;   // rows (t+256, t+384)
        const ulonglong2* dp = (const ulonglong2*)(sdup + k * EE);
#pragma unroll
        for (int e = 0; e < EE / 2; e++) {
            ulonglong2 d0 = dp[e];            // dict k,  elems 2e,2e+1 (dup)
            ulonglong2 d1 = dp[e + EE / 2];   // dict k+1
            fma2(a0, muA[2 * e],     d0.x);
            fma2(b0, muB[2 * e],     d0.x);
            fma2(a1, muA[2 * e],     d1.x);
            fma2(b1, muB[2 * e],     d1.x);
            fma2(a0, muA[2 * e + 1], d0.y);
            fma2(b0, muB[2 * e + 1], d0.y);
            fma2(a1, muA[2 * e + 1], d1.y);
            fma2(b1, muB[2 * e + 1], d1.y);
        }
        float s0, s1;
        unpack2(s0, s1, a0);
        if (s0 > best0) { best0 = s0; i0 = k; }
        if (s1 > best1) { best1 = s1; i1 = k; }
        unpack2(s0, s1, b0);
        if (s0 > best2) { best2 = s0; i2 = k; }
        if (s1 > best3) { best3 = s1; i3 = k; }
        unpack2(s0, s1, a1);
        if (s0 > best0) { best0 = s0; i0 = k + 1; }
        if (s1 > best1) { best1 = s1; i1 = k + 1; }
        unpack2(s0, s1, b1);
        if (s0 > best2) { best2 = s0; i2 = k + 1; }
        if (s1 > best3) { best3 = s1; i3 = k + 1; }
    }

    sidx[t]       = i0;
    sidx[t + 128] = i1;
    sidx[t + 256] = i2;
    sidx[t + 384] = i3;
    __syncthreads();

    // ---- write z and z_embed (cooperative, coalesced in 64B groups) ----
    {
        const float* sf = (const float*)sdup;   // low halves, stride 2
        for (int j = t; j < BB * EE / 4; j += NT) {   // 2048 float4 per block
            int row = j >> 2;
            int e4  = (j & 3) * 4;
            int kk  = sidx[row];
            int base = (kk * EE + e4) * 2;
            float4 v = make_float4(sf[base], sf[base + 2], sf[base + 4], sf[base + 6]);
            size_t off = (size_t)row * (CC * EE) + c * EE + e4;
            float4 m = *(const float4*)(mu + off);
            float4 z;
            z.x = m.x + (v.x - m.x);
            z.y = m.y + (v.y - m.y);
            z.z = m.z + (v.z - m.z);
            z.w = m.w + (v.w - m.w);
            *(float4*)(out + Z_OFF + off)  = z;
            *(float4*)(out + ZE_OFF + off) = v;
        }
    }

    // ---- scatter the ones ----
    for (int r = t; r < BB; r += NT) {
        out[OH_OFF + (size_t)r * (CC * KK) + (size_t)c * KK + sidx[r]] = 1.0f;
    }
}

extern "C" void kernel_launch(void* const* d_in, const int* in_sizes, int n_in,
                              void* d_out, int out_size)
{
    (void)in_sizes; (void)n_in; (void)out_size;
    const float* mu   = (const float*)d_in[0];
    const float* dict = (const float*)d_in[1];
    float* out = (float*)d_out;

    const int smem = (KK * EE + KK) * 8 + BB * 4;   // 71,680 bytes
    cudaFuncSetAttribute(vq_kernel, cudaFuncAttributeMaxDynamicSharedMemorySize, smem);
    vq_kernel<<<CC, NT, smem>>>(mu, dict, out);
}

// round 2
// speedup vs baseline: 1.9754x; 1.9754x over previous
#include <cuda_runtime.h>

#define BB   512
#define CC   512
#define KK   512
#define EE   16
#define NT   256

#define Z_OFF   0
#define ZE_OFF  ((size_t)BB * CC * EE)            // 4,194,304 floats
#define OH_OFF  ((size_t)2 * BB * CC * EE)        // 8,388,608 floats

typedef unsigned long long u64;

__device__ __forceinline__ u64 pack2(float a, float b) {
    u64 r;
    asm("mov.b64 %0, {%1, %2};" : "=l"(r) : "f"(a), "f"(b));
    return r;
}
__device__ __forceinline__ void fma2(u64 &d, u64 a, u64 b) {
    asm("fma.rn.f32x2 %0, %1, %2, %0;" : "+l"(d) : "l"(a), "l"(b));
}
__device__ __forceinline__ void unpack2(float &lo, float &hi, u64 v) {
    asm("mov.b64 {%0, %1}, %2;" : "=f"(lo), "=f"(hi) : "l"(v));
}

// Dynamic smem (34,816 B): sdict float[KK*EE] (32 KB, natural layout), snrm float[KK] (2 KB)
__global__ void __launch_bounds__(NT) vq_kernel(const float* __restrict__ mu,
                                                const float* __restrict__ dict,
                                                float* __restrict__ out)
{
    extern __shared__ float smem_f[];
    float* sdict = smem_f;              // KK*EE floats
    float* snrm  = smem_f + KK * EE;    // KK floats

    const int c = blockIdx.x;
    const int t = threadIdx.x;

    // ---- this thread's 2 batch rows (t, t+256), packed pairwise over e ----
    u64 muA[EE / 2], muB[EE / 2];
    {
        const float* m0 = mu + (size_t)t          * (CC * EE) + c * EE;
        const float* m1 = mu + (size_t)(t + 256)  * (CC * EE) + c * EE;
#pragma unroll
        for (int e = 0; e < EE; e += 4) {
            float4 a = *(const float4*)(m0 + e);
            float4 b = *(const float4*)(m1 + e);
            muA[e / 2]     = pack2(a.x, a.y);
            muA[e / 2 + 1] = pack2(a.z, a.w);
            muB[e / 2]     = pack2(b.x, b.y);
            muB[e / 2 + 1] = pack2(b.z, b.w);
        }
    }

    // ---- dict[c] -> smem (natural layout) ----
    {
        const float4* g = (const float4*)(dict + (size_t)c * KK * EE);
        float4* sd4 = (float4*)sdict;
#pragma unroll 4
        for (int i = t; i < KK * EE / 4; i += NT) sd4[i] = g[i];
    }
    __syncthreads();

    // ---- -0.5 * ||d_k||^2 ----
#pragma unroll
    for (int k = t; k < KK; k += NT) {
        const float4* dv = (const float4*)(sdict + k * EE);
        float s = 0.f;
#pragma unroll
        for (int j = 0; j < 4; j++) {
            float4 v = dv[j];
            s = fmaf(v.x, v.x, s); s = fmaf(v.y, v.y, s);
            s = fmaf(v.z, v.z, s); s = fmaf(v.w, v.w, s);
        }
        snrm[k] = -0.5f * s;
    }
    __syncthreads();

    // ---- one_hot zero-store cursor: this thread covers col4 = t&127 of rows 2*it + (t>>7) ----
    const float4 z4 = make_float4(0.f, 0.f, 0.f, 0.f);
    float4* ohp = (float4*)(out + OH_OFF)
                + (size_t)(t >> 7) * (CC * KK / 4)
                + (size_t)c * (KK / 4) + (t & 127);
    const size_t OH_STEP = 2 * ((size_t)CC * KK / 4);   // 2 batch rows per iter

    // ---- main argmax loop (k-pairs), zero stores interleaved ----
    float best0 = -3.4e38f, best1 = -3.4e38f;
    int i0 = 0, i1 = 0;
    const ulonglong2* dq = (const ulonglong2*)sdict;    // 8 per k-pair

    for (int it = 0; it < KK / 2; ++it) {
        const int k = 2 * it;
        *ohp = z4; ohp += OH_STEP;                      // fire-and-forget zero

        float n0 = snrm[k], n1 = snrm[k + 1];
        float lo, hi, s;

        {   // k
            ulonglong2 q0 = dq[0], q1 = dq[1], q2 = dq[2], q3 = dq[3];
            u64 a0 = 0, a1 = 0;
            fma2(a0, muA[0], q0.x); fma2(a1, muB[0], q0.x);
            fma2(a0, muA[1], q0.y); fma2(a1, muB[1], q0.y);
            fma2(a0, muA[2], q1.x); fma2(a1, muB[2], q1.x);
            fma2(a0, muA[3], q1.y); fma2(a1, muB[3], q1.y);
            fma2(a0, muA[4], q2.x); fma2(a1, muB[4], q2.x);
            fma2(a0, muA[5], q2.y); fma2(a1, muB[5], q2.y);
            fma2(a0, muA[6], q3.x); fma2(a1, muB[6], q3.x);
            fma2(a0, muA[7], q3.y); fma2(a1, muB[7], q3.y);
            unpack2(lo, hi, a0); s = lo + hi + n0;
            if (s > best0) { best0 = s; i0 = k; }
            unpack2(lo, hi, a1); s = lo + hi + n0;
            if (s > best1) { best1 = s; i1 = k; }
        }
        {   // k+1
            ulonglong2 q4 = dq[4], q5 = dq[5], q6 = dq[6], q7 = dq[7];
            u64 a2 = 0, a3 = 0;
            fma2(a2, muA[0], q4.x); fma2(a3, muB[0], q4.x);
            fma2(a2, muA[1], q4.y); fma2(a3, muB[1], q4.y);
            fma2(a2, muA[2], q5.x); fma2(a3, muB[2], q5.x);
            fma2(a2, muA[3], q5.y); fma2(a3, muB[3], q5.y);
            fma2(a2, muA[4], q6.x); fma2(a3, muB[4], q6.x);
            fma2(a2, muA[5], q6.y); fma2(a3, muB[5], q6.y);
            fma2(a2, muA[6], q7.x); fma2(a3, muB[6], q7.x);
            fma2(a2, muA[7], q7.y); fma2(a3, muB[7], q7.y);
            unpack2(lo, hi, a2); s = lo + hi + n1;
            if (s > best0) { best0 = s; i0 = k + 1; }
            unpack2(lo, hi, a3); s = lo + hi + n1;
            if (s > best1) { best1 = s; i1 = k + 1; }
        }
        dq += 8;
    }

    __syncthreads();   // all zero-stores block-visible before the ones land

    // ---- z / z_embed from registers + dict smem; scatter ones ----
    {
        const float* v = sdict + i0 * EE;
        size_t off = (size_t)t * (CC * EE) + c * EE;
#pragma unroll
        for (int e = 0; e < EE; e += 4) {
            float4 vv = *(const float4*)(v + e);
            float mx, my, mz, mw;
            unpack2(mx, my, muA[e / 2]);
            unpack2(mz, mw, muA[e / 2 + 1]);
            float4 zz;
            zz.x = mx + (vv.x - mx); zz.y = my + (vv.y - my);
            zz.z = mz + (vv.z - mz); zz.w = mw + (vv.w - mw);
            *(float4*)(out + Z_OFF  + off + e) = zz;
            *(float4*)(out + ZE_OFF + off + e) = vv;
        }
        out[OH_OFF + (size_t)t * (CC * KK) + (size_t)c * KK + i0] = 1.0f;
    }
    {
        const float* v = sdict + i1 * EE;
        size_t off = (size_t)(t + 256) * (CC * EE) + c * EE;
#pragma unroll
        for (int e = 0; e < EE; e += 4) {
            float4 vv = *(const float4*)(v + e);
            float mx, my, mz, mw;
            unpack2(mx, my, muB[e / 2]);
            unpack2(mz, mw, muB[e / 2 + 1]);
            float4 zz;
            zz.x = mx + (vv.x - mx); zz.y = my + (vv.y - my);
            zz.z = mz + (vv.z - mz); zz.w = mw + (vv.w - mw);
            *(float4*)(out + Z_OFF  + off + e) = zz;
            *(float4*)(out + ZE_OFF + off + e) = vv;
        }
        out[OH_OFF + (size_t)(t + 256) * (CC * KK) + (size_t)c * KK + i1] = 1.0f;
    }
}

extern "C" void kernel_launch(void* const* d_in, const int* in_sizes, int n_in,
                              void* d_out, int out_size)
{
    (void)in_sizes; (void)n_in; (void)out_size;
    const float* mu   = (const float*)d_in[0];
    const float* dict = (const float*)d_in[1];
    float* out = (float*)d_out;

    const int smem = (KK * EE + KK) * 4;   // 34,816 bytes
    cudaFuncSetAttribute(vq_kernel, cudaFuncAttributeMaxDynamicSharedMemorySize, smem);
    vq_kernel<<<CC, NT, smem>>>(mu, dict, out);
}